// round 6
// baseline (speedup 1.0000x reference)
#include <cuda_runtime.h>
#include <cuda_bf16.h>

// Skipgram negative-sampling loss, single fused kernel.
// Layout: each 16-lane half-warp owns one sample (2 samples/warp).
// Lane l (0..15) owns row float4s {l, l+16} -> each warp LDG.128 covers
// 4 line-aligned 128B segments (2 per sample) = full coalescing.
// k processed in two chunks to keep <=6 live dot registers.

#define NN   65536
#define KK   10
#define GRID 4096            // 4096 blocks * 8 warps * 2 samples = 65536

__device__ float    g_sum;
__device__ unsigned g_done;

__device__ __forceinline__ float log_sigmoid(float x) {
    float t = __expf(-fabsf(x));
    return fminf(x, 0.0f) - __logf(1.0f + t);
}

__device__ __forceinline__ float dot4(float4 a, float4 b) {
    return fmaf(a.x, b.x, fmaf(a.y, b.y, fmaf(a.z, b.z, a.w * b.w)));
}

__global__ __launch_bounds__(256, 5) void skipgram_fused_kernel(
    const int* __restrict__ input_idx,
    const int* __restrict__ output_idx,
    const int* __restrict__ neg_idx,
    const float4* __restrict__ W_in,    // rows of 32 float4
    const float4* __restrict__ W_out,
    float* __restrict__ out)
{
    const int lane = threadIdx.x & 31;
    const int wid  = threadIdx.x >> 5;
    const int g    = lane >> 4;          // half-warp 0/1
    const int l    = lane & 15;          // lane within group
    const int i    = ((((blockIdx.x << 3) | wid) << 1) | g);  // sample id

    const int ii = __ldg(&input_idx[i]);
    const int oi = __ldg(&output_idx[i]);
    const int* nidx = neg_idx + i * KK;

    const float4* arow = W_in + ii * 32 + l;
    const float4 a0 = __ldg(arow +  0);
    const float4 a1 = __ldg(arow + 16);

    float loss = 0.0f;   // valid on l==0 only

    // ---- chunk 0: positive + negatives 0..4 (6 parallel dot chains) ----
    {
        float d[6];
        {
            const float4* r = W_out + oi * 32 + l;
            d[0] = dot4(a0, __ldg(r)) + dot4(a1, __ldg(r + 16));
        }
        #pragma unroll
        for (int k = 0; k < 5; k++) {
            const int ni = __ldg(&nidx[k]);
            const float4* r = W_out + ni * 32 + l;
            d[k + 1] = dot4(a0, __ldg(r)) + dot4(a1, __ldg(r + 16));
        }
        #pragma unroll
        for (int s = 8; s > 0; s >>= 1)
            #pragma unroll
            for (int k = 0; k < 6; k++)
                d[k] += __shfl_xor_sync(0xffffffffu, d[k], s);
        if (l == 0) {
            loss = log_sigmoid(d[0]);
            #pragma unroll
            for (int k = 1; k < 6; k++) loss += log_sigmoid(-d[k]);
        }
    }

    // ---- chunk 1: negatives 5..9 (5 parallel dot chains) ----
    {
        float d[5];
        #pragma unroll
        for (int k = 0; k < 5; k++) {
            const int ni = __ldg(&nidx[5 + k]);
            const float4* r = W_out + ni * 32 + l;
            d[k] = dot4(a0, __ldg(r)) + dot4(a1, __ldg(r + 16));
        }
        #pragma unroll
        for (int s = 8; s > 0; s >>= 1)
            #pragma unroll
            for (int k = 0; k < 5; k++)
                d[k] += __shfl_xor_sync(0xffffffffu, d[k], s);
        if (l == 0) {
            #pragma unroll
            for (int k = 0; k < 5; k++) loss += log_sigmoid(-d[k]);
        }
    }

    // Block reduction: 16 leader values (8 warps * 2 groups) -> one atomic.
    __shared__ float ssum[16];
    if (l == 0) ssum[(wid << 1) | g] = loss;
    __syncthreads();

    if (threadIdx.x == 0) {
        float s = 0.0f;
        #pragma unroll
        for (int w = 0; w < 16; w++) s += ssum[w];
        atomicAdd(&g_sum, s);
        __threadfence();
        unsigned old = atomicAdd(&g_done, 1u);
        if (old == (unsigned)(GRID - 1)) {
            float total = atomicAdd(&g_sum, 0.0f);
            out[0] = total * (1.0f / (float)NN);
            g_sum  = 0.0f;
            g_done = 0u;
        }
    }
}

extern "C" void kernel_launch(void* const* d_in, const int* in_sizes, int n_in,
                              void* d_out, int out_size) {
    const int*    input_idx  = (const int*)d_in[0];
    const int*    output_idx = (const int*)d_in[1];
    const int*    neg_idx    = (const int*)d_in[2];
    const float4* W_in       = (const float4*)d_in[3];
    const float4* W_out      = (const float4*)d_in[4];
    float*        out        = (float*)d_out;

    skipgram_fused_kernel<<<GRID, 256>>>(input_idx, output_idx, neg_idx,
                                         W_in, W_out, out);
}

// round 10
// speedup vs baseline: 1.1358x; 1.1358x over previous
#include <cuda_runtime.h>
#include <cuda_bf16.h>

// Skipgram negative-sampling loss, single fused kernel.
// Layout: each 8-lane group of a warp owns one sample (4 samples/warp).
// Lane l of a group owns row float4s {j*8 + l : j=0..3} -> each warp LDG.128
// covers 4 line-aligned 128B segments (one per sample) = full coalescing.
// neg_idx loaded as 5x int2 (40B per sample, always 8B-aligned).

#define NN   65536
#define KK   10
#define GRID 2048            // 2048 blocks * 8 warps * 4 samples = 65536

__device__ float    g_sum;
__device__ unsigned g_done;

__device__ __forceinline__ float log_sigmoid(float x) {
    float t = __expf(-fabsf(x));
    return fminf(x, 0.0f) - __logf(1.0f + t);
}

__device__ __forceinline__ float dot4(float4 a, float4 b) {
    return fmaf(a.x, b.x, fmaf(a.y, b.y, fmaf(a.z, b.z, a.w * b.w)));
}

__global__ __launch_bounds__(256, 4) void skipgram_fused_kernel(
    const int* __restrict__ input_idx,
    const int* __restrict__ output_idx,
    const int* __restrict__ neg_idx,
    const float4* __restrict__ W_in,    // rows of 32 float4
    const float4* __restrict__ W_out,
    float* __restrict__ out)
{
    const int lane = threadIdx.x & 31;
    const int wid  = threadIdx.x >> 5;
    const int g    = lane >> 3;         // group 0..3 within warp
    const int l    = lane & 7;          // lane 0..7 within group
    const int i    = ((((blockIdx.x << 3) | wid) << 2) | g);  // sample id

    // ---- all index loads first (independent, shortest dependent front) ----
    const int ii = __ldg(&input_idx[i]);
    const int oi = __ldg(&output_idx[i]);
    const int2* nv = (const int2*)(neg_idx + i * KK);   // 40B -> 5x int2, 8B-aligned
    const int2 n01 = __ldg(nv + 0);
    const int2 n23 = __ldg(nv + 1);
    const int2 n45 = __ldg(nv + 2);
    const int2 n67 = __ldg(nv + 3);
    const int2 n89 = __ldg(nv + 4);
    int ni[KK];
    ni[0] = n01.x; ni[1] = n01.y; ni[2] = n23.x; ni[3] = n23.y;
    ni[4] = n45.x; ni[5] = n45.y; ni[6] = n67.x; ni[7] = n67.y;
    ni[8] = n89.x; ni[9] = n89.y;

    // ---- row loads: a-row then 11 gather rows, all independent ----
    const float4* arow = W_in + ii * 32 + l;
    const float4 a0 = __ldg(arow +  0);
    const float4 a1 = __ldg(arow +  8);
    const float4 a2 = __ldg(arow + 16);
    const float4 a3 = __ldg(arow + 24);

    float dots[KK + 1];
    {
        const float4* r = W_out + oi * 32 + l;
        dots[0] = dot4(a0, __ldg(r +  0)) + dot4(a1, __ldg(r +  8))
                + dot4(a2, __ldg(r + 16)) + dot4(a3, __ldg(r + 24));
    }
    #pragma unroll
    for (int k = 0; k < KK; k++) {
        const float4* r = W_out + ni[k] * 32 + l;
        dots[k + 1] = dot4(a0, __ldg(r +  0)) + dot4(a1, __ldg(r +  8))
                    + dot4(a2, __ldg(r + 16)) + dot4(a3, __ldg(r + 24));
    }

    // Reduce within 8-lane groups: 3 butterfly steps, 11 dots interleaved.
    #pragma unroll
    for (int s = 4; s > 0; s >>= 1) {
        #pragma unroll
        for (int k = 0; k <= KK; k++)
            dots[k] += __shfl_xor_sync(0xffffffffu, dots[k], s);
    }

    float loss = 0.0f;
    if (l == 0) {   // 4 group leaders per warp
        loss = log_sigmoid(dots[0]);
        #pragma unroll
        for (int k = 1; k <= KK; k++) loss += log_sigmoid(-dots[k]);
    }

    // Block reduction: 32 leader values -> one atomic per block.
    __shared__ float ssum[32];
    if (l == 0) ssum[(wid << 2) | g] = loss;
    __syncthreads();

    if (threadIdx.x == 0) {
        float s = 0.0f;
        #pragma unroll
        for (int w = 0; w < 32; w++) s += ssum[w];
        atomicAdd(&g_sum, s);
        __threadfence();
        unsigned old = atomicAdd(&g_done, 1u);
        if (old == (unsigned)(GRID - 1)) {
            float total = atomicAdd(&g_sum, 0.0f);
            out[0] = total * (1.0f / (float)NN);
            g_sum  = 0.0f;
            g_done = 0u;
        }
    }
}

extern "C" void kernel_launch(void* const* d_in, const int* in_sizes, int n_in,
                              void* d_out, int out_size) {
    const int*    input_idx  = (const int*)d_in[0];
    const int*    output_idx = (const int*)d_in[1];
    const int*    neg_idx    = (const int*)d_in[2];
    const float4* W_in       = (const float4*)d_in[3];
    const float4* W_out      = (const float4*)d_in[4];
    float*        out        = (float*)d_out;

    skipgram_fused_kernel<<<GRID, 256>>>(input_idx, output_idx, neg_idx,
                                         W_in, W_out, out);
}

// round 11
// speedup vs baseline: 1.1577x; 1.0192x over previous
#include <cuda_runtime.h>
#include <cuda_bf16.h>

// Skipgram negative-sampling loss, single fused kernel.
// Layout: each 8-lane group of a warp owns one sample (4 samples/warp).
// 128-thread blocks (16 samples) for fine scheduling granularity.
// Two-level completion counters avoid contended-ATOMG serialization.

#define NN      65536
#define KK      10
#define TPB     128
#define GRID    4096          // 4096 blocks * 4 warps * 4 samples = 65536
#define STRIPES 64            // GRID / STRIPES = 64 blocks per stripe

__device__ float    g_sum;
__device__ unsigned g_done1[STRIPES];   // per-stripe arrival counters
__device__ unsigned g_done2;            // stripe-completion counter

__device__ __forceinline__ float log_sigmoid(float x) {
    float t = __expf(-fabsf(x));
    return fminf(x, 0.0f) - __logf(1.0f + t);
}

__device__ __forceinline__ float dot4(float4 a, float4 b) {
    return fmaf(a.x, b.x, fmaf(a.y, b.y, fmaf(a.z, b.z, a.w * b.w)));
}

__global__ __launch_bounds__(TPB, 8) void skipgram_fused_kernel(
    const int* __restrict__ input_idx,
    const int* __restrict__ output_idx,
    const int* __restrict__ neg_idx,
    const float4* __restrict__ W_in,    // rows of 32 float4
    const float4* __restrict__ W_out,
    float* __restrict__ out)
{
    const int lane = threadIdx.x & 31;
    const int wid  = threadIdx.x >> 5;           // 0..3
    const int g    = lane >> 3;                  // group 0..3 within warp
    const int l    = lane & 7;                   // lane 0..7 within group
    const int i    = ((((blockIdx.x << 2) | wid) << 2) | g);  // sample id

    // ---- all index loads first (independent, shortest dependent front) ----
    const int ii = __ldg(&input_idx[i]);
    const int oi = __ldg(&output_idx[i]);
    const int2* nv = (const int2*)(neg_idx + i * KK);   // 40B -> 5x int2, 8B-aligned
    const int2 n01 = __ldg(nv + 0);
    const int2 n23 = __ldg(nv + 1);
    const int2 n45 = __ldg(nv + 2);
    const int2 n67 = __ldg(nv + 3);
    const int2 n89 = __ldg(nv + 4);
    int ni[KK];
    ni[0] = n01.x; ni[1] = n01.y; ni[2] = n23.x; ni[3] = n23.y;
    ni[4] = n45.x; ni[5] = n45.y; ni[6] = n67.x; ni[7] = n67.y;
    ni[8] = n89.x; ni[9] = n89.y;

    // ---- row loads: a-row then 11 gather rows, all independent ----
    const float4* arow = W_in + ii * 32 + l;
    const float4 a0 = __ldg(arow +  0);
    const float4 a1 = __ldg(arow +  8);
    const float4 a2 = __ldg(arow + 16);
    const float4 a3 = __ldg(arow + 24);

    float dots[KK + 1];
    {
        const float4* r = W_out + oi * 32 + l;
        dots[0] = dot4(a0, __ldg(r +  0)) + dot4(a1, __ldg(r +  8))
                + dot4(a2, __ldg(r + 16)) + dot4(a3, __ldg(r + 24));
    }
    #pragma unroll
    for (int k = 0; k < KK; k++) {
        const float4* r = W_out + ni[k] * 32 + l;
        dots[k + 1] = dot4(a0, __ldg(r +  0)) + dot4(a1, __ldg(r +  8))
                    + dot4(a2, __ldg(r + 16)) + dot4(a3, __ldg(r + 24));
    }

    // Reduce within 8-lane groups: 3 butterfly steps, 11 dots interleaved.
    #pragma unroll
    for (int s = 4; s > 0; s >>= 1) {
        #pragma unroll
        for (int k = 0; k <= KK; k++)
            dots[k] += __shfl_xor_sync(0xffffffffu, dots[k], s);
    }

    float loss = 0.0f;
    if (l == 0) {   // 4 group leaders per warp
        loss = log_sigmoid(dots[0]);
        #pragma unroll
        for (int k = 1; k <= KK; k++) loss += log_sigmoid(-dots[k]);
    }

    // Block reduction: 16 leader values -> one reduction-add per block.
    __shared__ float ssum[16];
    if (l == 0) ssum[(wid << 2) | g] = loss;
    __syncthreads();

    if (threadIdx.x == 0) {
        float s = 0.0f;
        #pragma unroll
        for (int w = 0; w < 16; w++) s += ssum[w];
        atomicAdd(&g_sum, s);        // return unused -> REDG path, ~0.854 cyc/op
        __threadfence();

        // Two-level completion: 64 blocks/stripe, then 64 stripes.
        const int stripe = blockIdx.x & (STRIPES - 1);
        unsigned o1 = atomicAdd(&g_done1[stripe], 1u);
        if (o1 == (GRID / STRIPES) - 1) {
            g_done1[stripe] = 0u;                 // reset for next replay
            __threadfence();
            unsigned o2 = atomicAdd(&g_done2, 1u);
            if (o2 == STRIPES - 1) {
                float total = atomicAdd(&g_sum, 0.0f);   // atomic read at L2
                out[0] = total * (1.0f / (float)NN);
                g_sum   = 0.0f;
                g_done2 = 0u;
            }
        }
    }
}

extern "C" void kernel_launch(void* const* d_in, const int* in_sizes, int n_in,
                              void* d_out, int out_size) {
    const int*    input_idx  = (const int*)d_in[0];
    const int*    output_idx = (const int*)d_in[1];
    const int*    neg_idx    = (const int*)d_in[2];
    const float4* W_in       = (const float4*)d_in[3];
    const float4* W_out      = (const float4*)d_in[4];
    float*        out        = (float*)d_out;

    skipgram_fused_kernel<<<GRID, TPB>>>(input_idx, output_idx, neg_idx,
                                         W_in, W_out, out);
}